// round 6
// baseline (speedup 1.0000x reference)
#include <cuda_runtime.h>

// y[4096] = x[1,5504] @ W[4096, act_idx[cluster]]^T + bias
// Fused single kernel, 148 blocks x 1024 threads.
// Block b owns a CONTIGUOUS chunk of 27-28 rows (one contiguous ~1.2MB W
// region). The chunk is split flat into 32 exactly-equal warp segments; each
// warp accumulates into <=2 rows (segment shorter than a row), reduces via
// shuffle, and combines per-row partials through shared-memory atomics.
// xs[11008] is densified in smem per block (zero -> gather -> smem atomics).

#define D_OUT 4096
#define D_IN 11008
#define NF4 (D_IN / 4)          // 2752 float4 per row
#define REMAINED 5504
#define THREADS 1024
#define NBLOCKS 148
#define MAX_ROWS 28

__global__ __launch_bounds__(THREADS, 1) void fused_gemv_kernel(
    const float* __restrict__ x,
    const float* __restrict__ weight,
    const float* __restrict__ bias,
    const int*   __restrict__ act_idx,
    const int*   __restrict__ cluster,
    float*       __restrict__ out)
{
    __shared__ float sxs[D_IN];      // 44032 B densified input
    __shared__ float srows[MAX_ROWS];

    // ---- block row range: 100 blocks x 28 rows + 48 blocks x 27 rows ----
    const int b = blockIdx.x;
    int nrows, row_base;
    if (b < 100) { nrows = 28; row_base = b * 28; }
    else         { nrows = 27; row_base = 2800 + (b - 100) * 27; }

    const float4* __restrict__ wflat =
        reinterpret_cast<const float4*>(weight + (size_t)row_base * D_IN);

    const int warp = threadIdx.x >> 5;
    const int lane = threadIdx.x & 31;

    const int total    = nrows * NF4;       // 77056 or 74304
    const int seg      = total >> 5;        // exact: 2408 or 2322
    const int seg_start = warp * seg;
    const int seg_end   = seg_start + seg;

    const int r0       = seg_start / NF4;          // first row this warp touches
    const int boundary = (r0 + 1) * NF4;           // flat idx where row r0 ends
    const int base0    = r0 * NF4;

    // ---- prefetch first two elements per lane BEFORE the prologue ----
    const int j0 = seg_start + lane;
    float4 p0 = __ldcs(wflat + j0);
    float4 p1 = __ldcs(wflat + j0 + 32);   // seg >= 2322 >> 64, always valid

    // ---- prologue: zero smem, densify xs ----
    float4* sxs4 = reinterpret_cast<float4*>(sxs);
    #pragma unroll
    for (int i = threadIdx.x; i < NF4; i += THREADS)
        sxs4[i] = make_float4(0.f, 0.f, 0.f, 0.f);
    if (threadIdx.x < MAX_ROWS) srows[threadIdx.x] = 0.f;
    __syncthreads();

    const int cl = *cluster;
    const int* idx_row = act_idx + cl * REMAINED;
    #pragma unroll
    for (int i = threadIdx.x; i < REMAINED; i += THREADS) {
        int   c = __ldg(idx_row + i);
        float v = __ldg(x + i);
        atomicAdd(&sxs[c], v);
    }
    __syncthreads();

    // ---- main stream: flat dot-product over the warp's segment ----
    const float4* sx4 = reinterpret_cast<const float4*>(sxs);
    float acc0 = 0.f, acc1 = 0.f;

    // consume prefetched pair
    {
        int c = j0 - ((j0 < boundary) ? base0 : boundary);
        float4 bb = sx4[c];
        float t = fmaf(p0.x, bb.x, fmaf(p0.y, bb.y, fmaf(p0.z, bb.z, p0.w * bb.w)));
        if (j0 < boundary) acc0 += t; else acc1 += t;
        int j1 = j0 + 32;
        int c1 = j1 - ((j1 < boundary) ? base0 : boundary);
        float4 bb1 = sx4[c1];
        float t1 = fmaf(p1.x, bb1.x, fmaf(p1.y, bb1.y, fmaf(p1.z, bb1.z, p1.w * bb1.w)));
        if (j1 < boundary) acc0 += t1; else acc1 += t1;
    }

    #pragma unroll 4
    for (int j = j0 + 64; j < seg_end; j += 32) {
        float4 a = __ldcs(wflat + j);
        int c = j - ((j < boundary) ? base0 : boundary);
        float4 bb = sx4[c];
        float t = fmaf(a.x, bb.x, fmaf(a.y, bb.y, fmaf(a.z, bb.z, a.w * bb.w)));
        if (j < boundary) acc0 += t; else acc1 += t;
    }

    // ---- warp reduce both accumulators, combine per-row in smem ----
    #pragma unroll
    for (int off = 16; off > 0; off >>= 1) {
        acc0 += __shfl_xor_sync(0xffffffffu, acc0, off);
        acc1 += __shfl_xor_sync(0xffffffffu, acc1, off);
    }
    if (lane == 0) {
        atomicAdd(&srows[r0], acc0);
        if (boundary < seg_end)            // warp actually crossed into row r0+1
            atomicAdd(&srows[r0 + 1], acc1);
    }
    __syncthreads();

    if (threadIdx.x < nrows) {
        int row = row_base + threadIdx.x;
        out[row] = srows[threadIdx.x] + bias[row];
    }
}

extern "C" void kernel_launch(void* const* d_in, const int* in_sizes, int n_in,
                              void* d_out, int out_size) {
    const float* x       = (const float*)d_in[0];   // (1, 5504)
    const float* weight  = (const float*)d_in[1];   // (4096, 11008)
    const float* bias    = (const float*)d_in[2];   // (4096,)
    const int*   act_idx = (const int*)d_in[3];     // (64, 5504) int32 (jax x64 off)
    const int*   cluster = (const int*)d_in[4];     // scalar int32
    float*       out     = (float*)d_out;           // (1, 4096)

    fused_gemv_kernel<<<NBLOCKS, THREADS>>>(x, weight, bias, act_idx, cluster, out);
}